// round 14
// baseline (speedup 1.0000x reference)
#include <cuda_runtime.h>
#include <cstdint>

#define T_DIM 8192
#define H_DIM 2048
#define D_DIM 1024
#define CHUNKS 64
#define CLEN 128            // T_DIM / CHUNKS

#define BM 128
#define BN 128
#define BK 32
#define SSTRIDE 36          // padded smem row stride (floats) for pipeline tiles
#define VSTRIDE 132         // padded smem row stride (floats) for epilogue V tiles
#define KT (D_DIM / BK)     // 32 k-tiles
// pipeline: 3 tensors (A,B1,B2) * 2 stages * 128*36 floats = 110592 B
// epilogue: 2 tensors * 128*132 floats = 135168 B  -> dynamic smem = max
#define PIPE_BYTES (3 * 2 * BM * SSTRIDE * 4)
#define EPI_BYTES  (2 * CLEN * VSTRIDE * 4)
#define SMEM_BYTES (EPI_BYTES > PIPE_BYTES ? EPI_BYTES : PIPE_BYTES)

// ---------------- device scratch -------------------------------------------------
__device__ float g_V1[(size_t)T_DIM * H_DIM];   // gamma * (x @ B1^T)
__device__ float g_V2[(size_t)T_DIM * H_DIM];   // gamma * (x @ B2^T)
__device__ float g_a[H_DIM], g_b[H_DIM], g_gamma[H_DIM];
__device__ float g_aL[H_DIM], g_bL[H_DIM];      // c^CLEN
__device__ float g_E1[CHUNKS * H_DIM], g_E2[CHUNKS * H_DIM];  // chunk-local scan ends
__device__ float g_P1[CHUNKS * H_DIM], g_P2[CHUNKS * H_DIM];  // chunk-start states

// ---------------- per-head parameters --------------------------------------------
__global__ void param_kernel(const float* __restrict__ lamda,
                             const float* __restrict__ theta) {
    int h = blockIdx.x * blockDim.x + threadIdx.x;
    if (h >= H_DIM) return;
    float y = expf(-expf(lamda[h]));
    float z = expf(theta[h]);
    float gamma = sqrtf(fmaxf(1.0f - y * y, 0.0f));
    float a = y * cosf(z);
    float b = y * sinf(z);
    g_a[h] = a; g_b[h] = b; g_gamma[h] = gamma;
    float ar = 1.0f, ai = 0.0f;
    #pragma unroll 8
    for (int i = 0; i < CLEN; i++) {
        float nr = ar * a - ai * b;
        float ni = ar * b + ai * a;
        ar = nr; ai = ni;
    }
    g_aL[h] = ar; g_bL[h] = ai;
}

// ---------------- fused dual GEMM + local scan -----------------------------------
__device__ __forceinline__ uint32_t f2tf32(float x) {
    uint32_t r;
    asm("cvt.rna.tf32.f32 %0, %1;" : "=r"(r) : "f"(x));
    return r;
}

__global__ __launch_bounds__(256, 1)
void gemm_scan_kernel(const float* __restrict__ X,
                      const float* __restrict__ B1,
                      const float* __restrict__ B2) {
    extern __shared__ float smem[];
    float* As  = smem;                              // [2][BM*SSTRIDE]
    float* B1s = smem + 2 * BM * SSTRIDE;           // [2][BN*SSTRIDE]
    float* B2s = smem + 4 * BM * SSTRIDE;           // [2][BN*SSTRIDE]

    const int tid = threadIdx.x;
    const int warp = tid >> 5, lane = tid & 31;
    const int wm = warp >> 2, wn = warp & 3;        // 2 x 4 warp grid, warp tile 64x32
    const int chunk = blockIdx.x;                   // M-tile == scan chunk
    const int m0 = chunk * BM;
    const int n0 = blockIdx.y * BN;

    float acc1[4][4][4], acc2[4][4][4];
    #pragma unroll
    for (int i = 0; i < 4; i++)
        #pragma unroll
        for (int j = 0; j < 4; j++)
            #pragma unroll
            for (int k = 0; k < 4; k++) { acc1[i][j][k] = 0.0f; acc2[i][j][k] = 0.0f; }

    auto issue = [&](int stage, int kt) {
        const int k0 = kt * BK;
        #pragma unroll
        for (int i = 0; i < 4; i++) {
            int c = tid + i * 256;                  // 1024 16B-chunks per tensor tile
            int row = c >> 3, cc = c & 7;
            const float* gA = X + (size_t)(m0 + row) * D_DIM + k0 + cc * 4;
            uint32_t dA = (uint32_t)__cvta_generic_to_shared(
                As + stage * BM * SSTRIDE + row * SSTRIDE + cc * 4);
            asm volatile("cp.async.cg.shared.global [%0], [%1], 16;" :: "r"(dA), "l"(gA));
            const float* gB1 = B1 + (size_t)(n0 + row) * D_DIM + k0 + cc * 4;
            uint32_t dB1 = (uint32_t)__cvta_generic_to_shared(
                B1s + stage * BM * SSTRIDE + row * SSTRIDE + cc * 4);
            asm volatile("cp.async.cg.shared.global [%0], [%1], 16;" :: "r"(dB1), "l"(gB1));
            const float* gB2 = B2 + (size_t)(n0 + row) * D_DIM + k0 + cc * 4;
            uint32_t dB2 = (uint32_t)__cvta_generic_to_shared(
                B2s + stage * BM * SSTRIDE + row * SSTRIDE + cc * 4);
            asm volatile("cp.async.cg.shared.global [%0], [%1], 16;" :: "r"(dB2), "l"(gB2));
        }
        asm volatile("cp.async.commit_group;");
    };

    issue(0, 0);
    for (int kt = 0; kt < KT; kt++) {
        if (kt + 1 < KT) {
            issue((kt + 1) & 1, kt + 1);
            asm volatile("cp.async.wait_group 1;");
        } else {
            asm volatile("cp.async.wait_group 0;");
        }
        __syncthreads();
        const float* Asb  = As  + (kt & 1) * BM * SSTRIDE;
        const float* B1sb = B1s + (kt & 1) * BM * SSTRIDE;
        const float* B2sb = B2s + (kt & 1) * BM * SSTRIDE;
        #pragma unroll
        for (int ks = 0; ks < 4; ks++) {
            const int kb = ks * 8;
            uint32_t af[4][4];
            #pragma unroll
            for (int mi = 0; mi < 4; mi++) {
                int r = wm * 64 + mi * 16 + (lane >> 2);
                int cidx = kb + (lane & 3);
                af[mi][0] = f2tf32(Asb[r * SSTRIDE + cidx]);
                af[mi][1] = f2tf32(Asb[(r + 8) * SSTRIDE + cidx]);
                af[mi][2] = f2tf32(Asb[r * SSTRIDE + cidx + 4]);
                af[mi][3] = f2tf32(Asb[(r + 8) * SSTRIDE + cidx + 4]);
            }
            uint32_t bf1[4][2], bf2[4][2];
            #pragma unroll
            for (int ni = 0; ni < 4; ni++) {
                int n = wn * 32 + ni * 8 + (lane >> 2);
                int kk = kb + (lane & 3);
                bf1[ni][0] = f2tf32(B1sb[n * SSTRIDE + kk]);
                bf1[ni][1] = f2tf32(B1sb[n * SSTRIDE + kk + 4]);
                bf2[ni][0] = f2tf32(B2sb[n * SSTRIDE + kk]);
                bf2[ni][1] = f2tf32(B2sb[n * SSTRIDE + kk + 4]);
            }
            #pragma unroll
            for (int mi = 0; mi < 4; mi++)
                #pragma unroll
                for (int ni = 0; ni < 4; ni++) {
                    asm volatile(
                        "mma.sync.aligned.m16n8k8.row.col.f32.tf32.tf32.f32 "
                        "{%0,%1,%2,%3}, {%4,%5,%6,%7}, {%8,%9}, {%0,%1,%2,%3};"
                        : "+f"(acc1[mi][ni][0]), "+f"(acc1[mi][ni][1]),
                          "+f"(acc1[mi][ni][2]), "+f"(acc1[mi][ni][3])
                        : "r"(af[mi][0]), "r"(af[mi][1]), "r"(af[mi][2]), "r"(af[mi][3]),
                          "r"(bf1[ni][0]), "r"(bf1[ni][1]));
                    asm volatile(
                        "mma.sync.aligned.m16n8k8.row.col.f32.tf32.tf32.f32 "
                        "{%0,%1,%2,%3}, {%4,%5,%6,%7}, {%8,%9}, {%0,%1,%2,%3};"
                        : "+f"(acc2[mi][ni][0]), "+f"(acc2[mi][ni][1]),
                          "+f"(acc2[mi][ni][2]), "+f"(acc2[mi][ni][3])
                        : "r"(af[mi][0]), "r"(af[mi][1]), "r"(af[mi][2]), "r"(af[mi][3]),
                          "r"(bf2[ni][0]), "r"(bf2[ni][1]));
                }
        }
        __syncthreads();
    }

    // ---- epilogue: scale by gamma, store V to gmem + smem, run chunk-local scan --
    float* Vs1 = smem;                      // [CLEN][VSTRIDE]
    float* Vs2 = smem + CLEN * VSTRIDE;     // [CLEN][VSTRIDE]
    #pragma unroll
    for (int mi = 0; mi < 4; mi++) {
        #pragma unroll
        for (int ni = 0; ni < 4; ni++) {
            int rl = wm * 64 + mi * 16 + (lane >> 2);
            int hl = wn * 32 + ni * 8 + 2 * (lane & 3);
            float gm0 = g_gamma[n0 + hl], gm1 = g_gamma[n0 + hl + 1];
            float2 a0 = make_float2(acc1[mi][ni][0] * gm0, acc1[mi][ni][1] * gm1);
            float2 a1 = make_float2(acc1[mi][ni][2] * gm0, acc1[mi][ni][3] * gm1);
            float2 c0 = make_float2(acc2[mi][ni][0] * gm0, acc2[mi][ni][1] * gm1);
            float2 c1 = make_float2(acc2[mi][ni][2] * gm0, acc2[mi][ni][3] * gm1);
            *(float2*)(Vs1 + rl * VSTRIDE + hl)       = a0;
            *(float2*)(Vs1 + (rl + 8) * VSTRIDE + hl) = a1;
            *(float2*)(Vs2 + rl * VSTRIDE + hl)       = c0;
            *(float2*)(Vs2 + (rl + 8) * VSTRIDE + hl) = c1;
            *(float2*)(g_V1 + (size_t)(m0 + rl) * H_DIM + n0 + hl)     = a0;
            *(float2*)(g_V1 + (size_t)(m0 + rl + 8) * H_DIM + n0 + hl) = a1;
            *(float2*)(g_V2 + (size_t)(m0 + rl) * H_DIM + n0 + hl)     = c0;
            *(float2*)(g_V2 + (size_t)(m0 + rl + 8) * H_DIM + n0 + hl) = c1;
        }
    }
    __syncthreads();
    if (tid < BN) {                         // one thread per head: 128-step local scan
        int h = n0 + tid;
        float a = g_a[h], b = g_b[h];
        float s1 = 0.0f, s2 = 0.0f;
        #pragma unroll 8
        for (int k = 0; k < CLEN; k++) {
            float v1 = Vs1[k * VSTRIDE + tid];
            float v2 = Vs2[k * VSTRIDE + tid];
            float nn1 = fmaf(a, s1, fmaf(-b, s2, v1));
            float nn2 = fmaf(a, s2, fmaf(b, s1, v2));
            s1 = nn1; s2 = nn2;
        }
        g_E1[chunk * H_DIM + h] = s1;
        g_E2[chunk * H_DIM + h] = s2;
    }
}

// ---------------- chunk-prefix scan (latency-fixed: batched loads) ---------------
__global__ void scan_prefix_kernel() {
    int h = blockIdx.x * blockDim.x + threadIdx.x;
    if (h >= H_DIM) return;
    float aL = g_aL[h], bL = g_bL[h];
    float p1 = 0.0f, p2 = 0.0f;
    for (int j0 = 0; j0 < CHUNKS; j0 += 8) {
        float e1[8], e2[8];
        #pragma unroll
        for (int u = 0; u < 8; u++) {
            e1[u] = g_E1[(j0 + u) * H_DIM + h];
            e2[u] = g_E2[(j0 + u) * H_DIM + h];
        }
        #pragma unroll
        for (int u = 0; u < 8; u++) {
            g_P1[(j0 + u) * H_DIM + h] = p1;
            g_P2[(j0 + u) * H_DIM + h] = p2;
            float n1 = fmaf(aL, p1, fmaf(-bL, p2, e1[u]));
            float n2 = fmaf(aL, p2, fmaf(bL, p1, e2[u]));
            p1 = n1; p2 = n2;
        }
    }
}

// ---------------- final scan: 2 heads/thread, float2 I/O, write [T, 2H] ----------
__global__ void scan_final_kernel(float* __restrict__ out) {
    int tid = blockIdx.x * blockDim.x + threadIdx.x;   // (H/2)*CHUNKS threads
    int h2 = tid & (H_DIM / 2 - 1);
    int chunk = tid >> 10;                             // H_DIM/2 = 1024 = 2^10
    int h = h2 * 2;
    float a0 = g_a[h],  b0 = g_b[h];
    float a1 = g_a[h + 1], b1 = g_b[h + 1];
    float2 s1 = *(const float2*)(g_P1 + chunk * H_DIM + h);
    float2 s2 = *(const float2*)(g_P2 + chunk * H_DIM + h);
    int base = chunk * CLEN * H_DIM + h;
    int obase = chunk * CLEN * 2 * H_DIM + h;
    #pragma unroll 4
    for (int k = 0; k < CLEN; k++) {
        float2 v1 = *(const float2*)(g_V1 + base + k * H_DIM);
        float2 v2 = *(const float2*)(g_V2 + base + k * H_DIM);
        float n1x = fmaf(a0, s1.x, fmaf(-b0, s2.x, v1.x));
        float n2x = fmaf(a0, s2.x, fmaf(b0, s1.x, v2.x));
        float n1y = fmaf(a1, s1.y, fmaf(-b1, s2.y, v1.y));
        float n2y = fmaf(a1, s2.y, fmaf(b1, s1.y, v2.y));
        s1 = make_float2(n1x, n1y);
        s2 = make_float2(n2x, n2y);
        *(float2*)(out + obase + k * 2 * H_DIM) = s1;
        *(float2*)(out + obase + k * 2 * H_DIM + H_DIM) = s2;
    }
}

// ---------------- launcher -------------------------------------------------------
extern "C" void kernel_launch(void* const* d_in, const int* in_sizes, int n_in,
                              void* d_out, int out_size) {
    const float* x     = (const float*)d_in[0];   // [T, D]
    const float* lamda = (const float*)d_in[1];   // [H]
    const float* theta = (const float*)d_in[2];   // [H]
    const float* B1    = (const float*)d_in[3];   // [H, D]
    const float* B2    = (const float*)d_in[4];   // [H, D]
    float* out = (float*)d_out;                   // [T, 2H]

    cudaFuncSetAttribute(gemm_scan_kernel,
                         cudaFuncAttributeMaxDynamicSharedMemorySize, SMEM_BYTES);

    param_kernel<<<(H_DIM + 255) / 256, 256>>>(lamda, theta);

    dim3 grid(T_DIM / BM, H_DIM / BN);            // (64, 16); M-tile == chunk
    gemm_scan_kernel<<<grid, 256, SMEM_BYTES>>>(x, B1, B2);

    scan_prefix_kernel<<<(H_DIM + 255) / 256, 256>>>();
    scan_final_kernel<<<(H_DIM / 2 * CHUNKS) / 256, 256>>>(out);
}

// round 17
// speedup vs baseline: 1.0583x; 1.0583x over previous
#include <cuda_runtime.h>
#include <cstdint>

#define T_DIM 8192
#define H_DIM 2048
#define D_DIM 1024
#define CHUNKS 128
#define CLEN 64             // T_DIM / CHUNKS

#define BM 128
#define BN 128
#define BK 32
#define SSTRIDE 36          // padded smem row stride (floats): bank-conflict-free frags
#define KT (D_DIM / BK)     // 32 k-tiles
#define SMEM_BYTES (2 * 2 * BM * SSTRIDE * 4)   // 73728 B -> 2 CTAs/SM fits

// ---------------- device scratch -------------------------------------------------
__device__ float g_Xr[(size_t)T_DIM * D_DIM];    // tf32-rounded inputs
__device__ float g_B1r[(size_t)H_DIM * D_DIM];
__device__ float g_B2r[(size_t)H_DIM * D_DIM];
__device__ float g_V1[(size_t)T_DIM * H_DIM];    // gamma * (x @ B1^T)
__device__ float g_V2[(size_t)T_DIM * H_DIM];
__device__ float g_a[H_DIM], g_b[H_DIM], g_gamma[H_DIM];
__device__ float g_aL[H_DIM], g_bL[H_DIM];       // c^CLEN
__device__ float g_E1[CHUNKS * H_DIM], g_E2[CHUNKS * H_DIM];
__device__ float g_P1[CHUNKS * H_DIM], g_P2[CHUNKS * H_DIM];

// ---------------- per-head parameters --------------------------------------------
__global__ void param_kernel(const float* __restrict__ lamda,
                             const float* __restrict__ theta) {
    int h = blockIdx.x * blockDim.x + threadIdx.x;
    if (h >= H_DIM) return;
    float y = expf(-expf(lamda[h]));
    float z = expf(theta[h]);
    float gamma = sqrtf(fmaxf(1.0f - y * y, 0.0f));
    float a = y * cosf(z);
    float b = y * sinf(z);
    g_a[h] = a; g_b[h] = b; g_gamma[h] = gamma;
    float ar = 1.0f, ai = 0.0f;
    #pragma unroll 8
    for (int i = 0; i < CLEN; i++) {
        float nr = ar * a - ai * b;
        float ni = ar * b + ai * a;
        ar = nr; ai = ni;
    }
    g_aL[h] = ar; g_bL[h] = ai;
}

// ---------------- tf32 rounding pre-pass -----------------------------------------
__device__ __forceinline__ float rna_tf32(float x) {
    uint32_t r;
    asm("cvt.rna.tf32.f32 %0, %1;" : "=r"(r) : "f"(x));
    return __uint_as_float(r);
}
#define NX4 (T_DIM * D_DIM / 4)
#define NB4 (H_DIM * D_DIM / 4)
__global__ void round_kernel(const float4* __restrict__ X,
                             const float4* __restrict__ B1,
                             const float4* __restrict__ B2) {
    int i = blockIdx.x * blockDim.x + threadIdx.x;
    const float4* src; float4* dst; int j;
    if (i < NX4)            { src = X;  dst = (float4*)g_Xr;  j = i; }
    else if (i < NX4 + NB4) { src = B1; dst = (float4*)g_B1r; j = i - NX4; }
    else                    { src = B2; dst = (float4*)g_B2r; j = i - NX4 - NB4; }
    float4 v = src[j];
    v.x = rna_tf32(v.x); v.y = rna_tf32(v.y);
    v.z = rna_tf32(v.z); v.w = rna_tf32(v.w);
    dst[j] = v;
}

// ---------------- tf32 GEMM (pre-rounded operands, no in-loop CVT) ----------------
__global__ __launch_bounds__(256, 2)
void gemm_kernel() {
    extern __shared__ float smem[];
    float* As = smem;                           // [2][BM*SSTRIDE]
    float* Bs = smem + 2 * BM * SSTRIDE;        // [2][BN*SSTRIDE]
    const float* Bmat = (blockIdx.z == 0) ? g_B1r : g_B2r;
    float* V = (blockIdx.z == 0) ? g_V1 : g_V2;

    const int tid = threadIdx.x;
    const int warp = tid >> 5, lane = tid & 31;
    const int wm = warp >> 2, wn = warp & 3;    // 2 x 4 warp grid, warp tile 64x32
    const int m0 = blockIdx.x * BM;
    const int n0 = blockIdx.y * BN;

    float acc[4][4][4];
    #pragma unroll
    for (int i = 0; i < 4; i++)
        #pragma unroll
        for (int j = 0; j < 4; j++)
            #pragma unroll
            for (int k = 0; k < 4; k++) acc[i][j][k] = 0.0f;

    auto issue = [&](int stage, int kt) {
        const int k0 = kt * BK;
        #pragma unroll
        for (int i = 0; i < 4; i++) {
            int c = tid + i * 256;              // 1024 16B-chunks per operand tile
            int row = c >> 3, cc = c & 7;
            const float* gA = g_Xr + (size_t)(m0 + row) * D_DIM + k0 + cc * 4;
            uint32_t dA = (uint32_t)__cvta_generic_to_shared(
                As + stage * BM * SSTRIDE + row * SSTRIDE + cc * 4);
            asm volatile("cp.async.cg.shared.global [%0], [%1], 16;" :: "r"(dA), "l"(gA));
            const float* gB = Bmat + (size_t)(n0 + row) * D_DIM + k0 + cc * 4;
            uint32_t dB = (uint32_t)__cvta_generic_to_shared(
                Bs + stage * BM * SSTRIDE + row * SSTRIDE + cc * 4);
            asm volatile("cp.async.cg.shared.global [%0], [%1], 16;" :: "r"(dB), "l"(gB));
        }
        asm volatile("cp.async.commit_group;");
    };

    issue(0, 0);
    for (int kt = 0; kt < KT; kt++) {
        if (kt + 1 < KT) {
            issue((kt + 1) & 1, kt + 1);
            asm volatile("cp.async.wait_group 1;");
        } else {
            asm volatile("cp.async.wait_group 0;");
        }
        __syncthreads();
        const uint32_t* Asb = (const uint32_t*)(As + (kt & 1) * BM * SSTRIDE);
        const uint32_t* Bsb = (const uint32_t*)(Bs + (kt & 1) * BM * SSTRIDE);
        #pragma unroll
        for (int ks = 0; ks < 4; ks++) {
            const int kb = ks * 8;
            uint32_t af[4][4];
            #pragma unroll
            for (int mi = 0; mi < 4; mi++) {
                int r = wm * 64 + mi * 16 + (lane >> 2);
                int cidx = kb + (lane & 3);
                af[mi][0] = Asb[r * SSTRIDE + cidx];
                af[mi][1] = Asb[(r + 8) * SSTRIDE + cidx];
                af[mi][2] = Asb[r * SSTRIDE + cidx + 4];
                af[mi][3] = Asb[(r + 8) * SSTRIDE + cidx + 4];
            }
            uint32_t bfr[4][2];
            #pragma unroll
            for (int ni = 0; ni < 4; ni++) {
                int n = wn * 32 + ni * 8 + (lane >> 2);
                int kk = kb + (lane & 3);
                bfr[ni][0] = Bsb[n * SSTRIDE + kk];
                bfr[ni][1] = Bsb[n * SSTRIDE + kk + 4];
            }
            #pragma unroll
            for (int mi = 0; mi < 4; mi++)
                #pragma unroll
                for (int ni = 0; ni < 4; ni++) {
                    asm volatile(
                        "mma.sync.aligned.m16n8k8.row.col.f32.tf32.tf32.f32 "
                        "{%0,%1,%2,%3}, {%4,%5,%6,%7}, {%8,%9}, {%0,%1,%2,%3};"
                        : "+f"(acc[mi][ni][0]), "+f"(acc[mi][ni][1]),
                          "+f"(acc[mi][ni][2]), "+f"(acc[mi][ni][3])
                        : "r"(af[mi][0]), "r"(af[mi][1]), "r"(af[mi][2]), "r"(af[mi][3]),
                          "r"(bfr[ni][0]), "r"(bfr[ni][1]));
                }
        }
        __syncthreads();
    }

    // epilogue: scale by gamma[h], store fp32
    #pragma unroll
    for (int mi = 0; mi < 4; mi++) {
        #pragma unroll
        for (int ni = 0; ni < 4; ni++) {
            int r = m0 + wm * 64 + mi * 16 + (lane >> 2);
            int h = n0 + wn * 32 + ni * 8 + 2 * (lane & 3);
            float gm0 = g_gamma[h], gm1 = g_gamma[h + 1];
            float2 v0 = make_float2(acc[mi][ni][0] * gm0, acc[mi][ni][1] * gm1);
            float2 v1 = make_float2(acc[mi][ni][2] * gm0, acc[mi][ni][3] * gm1);
            *(float2*)(V + (size_t)r * H_DIM + h) = v0;
            *(float2*)(V + (size_t)(r + 8) * H_DIM + h) = v1;
        }
    }
}

// ---------------- chunked scan ---------------------------------------------------
// Phase 1: per-(head,chunk) local scan from zero state; record chunk-end state.
__global__ void scan_local_kernel() {
    int tid = blockIdx.x * blockDim.x + threadIdx.x;   // H*CHUNKS threads
    int h = tid & (H_DIM - 1);
    int chunk = tid >> 11;                             // H_DIM = 2^11
    float a = g_a[h], b = g_b[h];
    float s1 = 0.0f, s2 = 0.0f;
    size_t base = (size_t)chunk * CLEN * H_DIM + h;
    #pragma unroll 4
    for (int k = 0; k < CLEN; k++) {
        float v1 = g_V1[base + (size_t)k * H_DIM];
        float v2 = g_V2[base + (size_t)k * H_DIM];
        float n1 = fmaf(a, s1, fmaf(-b, s2, v1));
        float n2 = fmaf(a, s2, fmaf(b, s1, v2));
        s1 = n1; s2 = n2;
    }
    g_E1[chunk * H_DIM + h] = s1;
    g_E2[chunk * H_DIM + h] = s2;
}

// Phase 2: per-head prefix over chunks (batched loads, MLP 16).
__global__ void scan_prefix_kernel() {
    int h = blockIdx.x * blockDim.x + threadIdx.x;
    if (h >= H_DIM) return;
    float aL = g_aL[h], bL = g_bL[h];
    float p1 = 0.0f, p2 = 0.0f;
    for (int j0 = 0; j0 < CHUNKS; j0 += 8) {
        float e1[8], e2[8];
        #pragma unroll
        for (int u = 0; u < 8; u++) {
            e1[u] = g_E1[(j0 + u) * H_DIM + h];
            e2[u] = g_E2[(j0 + u) * H_DIM + h];
        }
        #pragma unroll
        for (int u = 0; u < 8; u++) {
            g_P1[(j0 + u) * H_DIM + h] = p1;
            g_P2[(j0 + u) * H_DIM + h] = p2;
            float n1 = fmaf(aL, p1, fmaf(-bL, p2, e1[u]));
            float n2 = fmaf(aL, p2, fmaf(bL, p1, e2[u]));
            p1 = n1; p2 = n2;
        }
    }
}

// Phase 3: seeded local scans, 2 heads/thread, float2 I/O, write [T, 2H].
__global__ void scan_final_kernel(float* __restrict__ out) {
    int tid = blockIdx.x * blockDim.x + threadIdx.x;   // (H/2)*CHUNKS threads
    int h2 = tid & (H_DIM / 2 - 1);
    int chunk = tid >> 10;                             // H_DIM/2 = 1024 = 2^10
    int h = h2 * 2;
    float a0 = g_a[h],  b0 = g_b[h];
    float a1 = g_a[h + 1], b1 = g_b[h + 1];
    float2 s1 = *(const float2*)(g_P1 + chunk * H_DIM + h);
    float2 s2 = *(const float2*)(g_P2 + chunk * H_DIM + h);
    size_t base = (size_t)chunk * CLEN * H_DIM + h;
    size_t obase = (size_t)chunk * CLEN * 2 * H_DIM + h;
    #pragma unroll 4
    for (int k = 0; k < CLEN; k++) {
        float2 v1 = *(const float2*)(g_V1 + base + (size_t)k * H_DIM);
        float2 v2 = *(const float2*)(g_V2 + base + (size_t)k * H_DIM);
        float n1x = fmaf(a0, s1.x, fmaf(-b0, s2.x, v1.x));
        float n2x = fmaf(a0, s2.x, fmaf(b0, s1.x, v2.x));
        float n1y = fmaf(a1, s1.y, fmaf(-b1, s2.y, v1.y));
        float n2y = fmaf(a1, s2.y, fmaf(b1, s1.y, v2.y));
        s1 = make_float2(n1x, n1y);
        s2 = make_float2(n2x, n2y);
        *(float2*)(out + obase + (size_t)k * 2 * H_DIM) = s1;
        *(float2*)(out + obase + (size_t)k * 2 * H_DIM + H_DIM) = s2;
    }
}

// ---------------- launcher -------------------------------------------------------
extern "C" void kernel_launch(void* const* d_in, const int* in_sizes, int n_in,
                              void* d_out, int out_size) {
    const float* x     = (const float*)d_in[0];   // [T, D]
    const float* lamda = (const float*)d_in[1];   // [H]
    const float* theta = (const float*)d_in[2];   // [H]
    const float* B1    = (const float*)d_in[3];   // [H, D]
    const float* B2    = (const float*)d_in[4];   // [H, D]
    float* out = (float*)d_out;                   // [T, 2H]

    cudaFuncSetAttribute(gemm_kernel,
                         cudaFuncAttributeMaxDynamicSharedMemorySize, SMEM_BYTES);

    param_kernel<<<(H_DIM + 255) / 256, 256>>>(lamda, theta);
    round_kernel<<<(NX4 + 2 * NB4) / 256, 256>>>((const float4*)x, (const float4*)B1,
                                                 (const float4*)B2);

    dim3 grid(T_DIM / BM, H_DIM / BN, 2);         // (64, 16, 2)
    gemm_kernel<<<grid, 256, SMEM_BYTES>>>();

    scan_local_kernel<<<(H_DIM * CHUNKS) / 256, 256>>>();
    scan_prefix_kernel<<<(H_DIM + 255) / 256, 256>>>();
    scan_final_kernel<<<(H_DIM / 2 * CHUNKS) / 256, 256>>>(out);
}